// round 1
// baseline (speedup 1.0000x reference)
#include <cuda_runtime.h>

#define NN   50000
#define EE   800000
#define HID  128
#define NG   64
#define ODIM 64

// ---------------- device scratch (no allocations allowed) ----------------
__device__ float g_agg [NN * HID];
__device__ float g_bufA[NN * HID];
__device__ float g_bufB[NN * HID];
__device__ int   g_deg[NN];
__device__ int   g_rowptr[NN + 1];
__device__ int   g_cursor[NN];
__device__ int   g_csr_src[EE];
__device__ float g_WT[6][HID * HID];   // transposed weights: [in][out]
__device__ float g_pooled[NG * HID];
__device__ float g_counts[NG];

// ---------------- small utility kernels ----------------
__global__ void k_zero() {
    int i = blockIdx.x * blockDim.x + threadIdx.x;
    if (i < NN) g_deg[i] = 0;
    if (i < NG * HID) g_pooled[i] = 0.f;
    if (i < NG) g_counts[i] = 0.f;
}

__global__ void k_hist(const int* __restrict__ dst) {
    int e = blockIdx.x * blockDim.x + threadIdx.x;
    if (e < EE) atomicAdd(&g_deg[dst[e]], 1);
}

// single-block exclusive scan of g_deg -> g_rowptr
__global__ void k_scan() {
    __shared__ int ssum[1024];
    int tid = threadIdx.x;
    const int CH = (NN + 1023) / 1024;  // 49
    int base = tid * CH;
    int s = 0;
    for (int i = 0; i < CH; i++) {
        int idx = base + i;
        if (idx < NN) s += g_deg[idx];
    }
    ssum[tid] = s;
    __syncthreads();
    for (int off = 1; off < 1024; off <<= 1) {
        int v = (tid >= off) ? ssum[tid - off] : 0;
        __syncthreads();
        ssum[tid] += v;
        __syncthreads();
    }
    int run = (tid == 0) ? 0 : ssum[tid - 1];
    for (int i = 0; i < CH; i++) {
        int idx = base + i;
        if (idx < NN) { g_rowptr[idx] = run; run += g_deg[idx]; }
    }
    if (tid == 1023) g_rowptr[NN] = run;  // == EE
}

__global__ void k_copy_cursor() {
    int i = blockIdx.x * blockDim.x + threadIdx.x;
    if (i < NN) g_cursor[i] = g_rowptr[i];
}

__global__ void k_bin(const int* __restrict__ src, const int* __restrict__ dst) {
    int e = blockIdx.x * blockDim.x + threadIdx.x;
    if (e < EE) {
        int p = atomicAdd(&g_cursor[dst[e]], 1);
        g_csr_src[p] = src[e];
    }
}

// W [out=128][in=128] row-major  ->  g_WT[idx] [in][out]
__global__ void k_transpose(const float* __restrict__ W, int idx) {
    int i = blockIdx.x * blockDim.x + threadIdx.x;
    if (i < HID * HID) {
        int o = i / HID, k = i % HID;
        g_WT[idx][k * HID + o] = W[i];
    }
}

// ---------------- per-node neighbor aggregation (gather over CSR) ----------------
// one warp per node; lane owns 4 features (float4)
__global__ void k_aggregate(const float* __restrict__ xext, int insel) {
    const float* __restrict__ in =
        (insel < 0) ? xext : (insel == 0 ? g_bufA : g_bufB);
    int w    = (blockIdx.x * blockDim.x + threadIdx.x) >> 5;
    int lane = threadIdx.x & 31;
    if (w >= NN) return;
    int beg = g_rowptr[w], end = g_rowptr[w + 1];
    float4 acc = make_float4(0.f, 0.f, 0.f, 0.f);
    int e = beg;
    for (; e + 1 < end; e += 2) {
        int s0 = g_csr_src[e];
        int s1 = g_csr_src[e + 1];
        float4 v0 = *(const float4*)(in + (size_t)s0 * HID + lane * 4);
        float4 v1 = *(const float4*)(in + (size_t)s1 * HID + lane * 4);
        acc.x += v0.x; acc.y += v0.y; acc.z += v0.z; acc.w += v0.w;
        acc.x += v1.x; acc.y += v1.y; acc.z += v1.z; acc.w += v1.w;
    }
    if (e < end) {
        int s0 = g_csr_src[e];
        float4 v0 = *(const float4*)(in + (size_t)s0 * HID + lane * 4);
        acc.x += v0.x; acc.y += v0.y; acc.z += v0.z; acc.w += v0.w;
    }
    *(float4*)(g_agg + (size_t)w * HID + lane * 4) = acc;
}

// ---------------- fused SAGE linear:  C = relu?(agg@WlT + in@WrT + b) ----------------
// M=NN, N=128, K=128+128.  Block tile 128x128, 256 threads, 8x8 per thread.
__global__ __launch_bounds__(256) void k_gemm(
    const float* __restrict__ A2ext, int a2sel,
    int wl_idx, int wr_idx,
    const float* __restrict__ bias,
    int outsel, int doRelu)
{
    const float* __restrict__ A2 =
        (a2sel < 0) ? A2ext : (a2sel == 0 ? g_bufA : g_bufB);
    float* __restrict__ C = (outsel == 0) ? g_bufA : g_bufB;

    __shared__ float As[16][128];
    __shared__ float Bs[16][128];

    int tid = threadIdx.x;
    int tx = tid & 15;    // output col group
    int ty = tid >> 4;    // output row group (rows ty*8 .. ty*8+7)
    int m0 = blockIdx.x * 128;

    float acc[8][8];
#pragma unroll
    for (int i = 0; i < 8; i++)
#pragma unroll
        for (int j = 0; j < 8; j++) acc[i][j] = 0.f;

    int arow = tid & 127;   // row within tile for A loads
    int akq0 = tid >> 7;    // 0/1 -> k-quad base
    int bj   = (tid & 31) * 4;
    int bk0  = tid >> 5;    // 0..7

    const float* A  = g_agg;
    const float* BT = g_WT[wl_idx];
    for (int half = 0; half < 2; half++) {
        if (half) { A = A2; BT = g_WT[wr_idx]; }
        for (int k0 = 0; k0 < 128; k0 += 16) {
            // A tile -> As[k][m] (transposed), conflict-free stores
#pragma unroll
            for (int p = 0; p < 2; p++) {
                int kq = akq0 + p * 2;   // 0..3
                int grow = m0 + arow;
                float4 v = make_float4(0.f, 0.f, 0.f, 0.f);
                if (grow < NN)
                    v = *(const float4*)(A + (size_t)grow * HID + k0 + kq * 4);
                As[kq * 4 + 0][arow] = v.x;
                As[kq * 4 + 1][arow] = v.y;
                As[kq * 4 + 2][arow] = v.z;
                As[kq * 4 + 3][arow] = v.w;
            }
            // B tile: Bs[k][j] = WT[(k0+k)*128 + j], fully coalesced
#pragma unroll
            for (int p = 0; p < 2; p++) {
                int kr = bk0 + p * 8;
                *(float4*)&Bs[kr][bj] =
                    *(const float4*)(BT + (size_t)(k0 + kr) * HID + bj);
            }
            __syncthreads();
#pragma unroll
            for (int kk = 0; kk < 16; kk++) {
                float a[8], b[8];
                *(float4*)&a[0] = *(const float4*)&As[kk][ty * 8];
                *(float4*)&a[4] = *(const float4*)&As[kk][ty * 8 + 4];
                *(float4*)&b[0] = *(const float4*)&Bs[kk][tx * 4];
                *(float4*)&b[4] = *(const float4*)&Bs[kk][64 + tx * 4];
#pragma unroll
                for (int i = 0; i < 8; i++)
#pragma unroll
                    for (int j = 0; j < 8; j++)
                        acc[i][j] = fmaf(a[i], b[j], acc[i][j]);
            }
            __syncthreads();
        }
    }

    // epilogue: cols = tx*4+{0..3} and 64+tx*4+{0..3}
    float bv0[4], bv1[4];
#pragma unroll
    for (int j = 0; j < 4; j++) {
        bv0[j] = bias[tx * 4 + j];
        bv1[j] = bias[64 + tx * 4 + j];
    }
#pragma unroll
    for (int i = 0; i < 8; i++) {
        int grow = m0 + ty * 8 + i;
        if (grow >= NN) continue;
        float4 v0, v1;
        v0.x = acc[i][0] + bv0[0]; v0.y = acc[i][1] + bv0[1];
        v0.z = acc[i][2] + bv0[2]; v0.w = acc[i][3] + bv0[3];
        v1.x = acc[i][4] + bv1[0]; v1.y = acc[i][5] + bv1[1];
        v1.z = acc[i][6] + bv1[2]; v1.w = acc[i][7] + bv1[3];
        if (doRelu) {
            v0.x = fmaxf(v0.x, 0.f); v0.y = fmaxf(v0.y, 0.f);
            v0.z = fmaxf(v0.z, 0.f); v0.w = fmaxf(v0.w, 0.f);
            v1.x = fmaxf(v1.x, 0.f); v1.y = fmaxf(v1.y, 0.f);
            v1.z = fmaxf(v1.z, 0.f); v1.w = fmaxf(v1.w, 0.f);
        }
        *(float4*)(C + (size_t)grow * HID + tx * 4)      = v0;
        *(float4*)(C + (size_t)grow * HID + 64 + tx * 4) = v1;
    }
}

// ---------------- global mean pool (sum + counts), batch is sorted ----------------
__global__ void k_pool(const int* __restrict__ batch) {
    const float* __restrict__ h = g_bufA;  // layer-3 output lives here
    const int NPW = 16;                    // nodes per warp
    int w    = (blockIdx.x * blockDim.x + threadIdx.x) >> 5;
    int lane = threadIdx.x & 31;
    int n0 = w * NPW;
    if (n0 >= NN) return;
    int n1 = min(n0 + NPW, NN);
    float4 acc = make_float4(0.f, 0.f, 0.f, 0.f);
    int cg = -1, cnt = 0;
    for (int n = n0; n < n1; n++) {
        int g = batch[n];
        if (g != cg) {
            if (cg >= 0) {
                float* p = g_pooled + cg * HID + lane * 4;
                atomicAdd(p + 0, acc.x); atomicAdd(p + 1, acc.y);
                atomicAdd(p + 2, acc.z); atomicAdd(p + 3, acc.w);
                if (lane == 0) atomicAdd(&g_counts[cg], (float)cnt);
            }
            cg = g; acc = make_float4(0.f, 0.f, 0.f, 0.f); cnt = 0;
        }
        float4 v = *(const float4*)(h + (size_t)n * HID + lane * 4);
        acc.x += v.x; acc.y += v.y; acc.z += v.z; acc.w += v.w;
        cnt++;
    }
    if (cg >= 0) {
        float* p = g_pooled + cg * HID + lane * 4;
        atomicAdd(p + 0, acc.x); atomicAdd(p + 1, acc.y);
        atomicAdd(p + 2, acc.z); atomicAdd(p + 3, acc.w);
        if (lane == 0) atomicAdd(&g_counts[cg], (float)cnt);
    }
}

// ---------------- final linear: out[g][o] = (pooled[g]/count[g]) . Wlin[o] + blin[o]
__global__ void k_final(const float* __restrict__ Wlin,
                        const float* __restrict__ blin,
                        float* __restrict__ out) {
    __shared__ float p[HID];
    int g = blockIdx.x, o = threadIdx.x;  // 64 x 64
    p[o]      = g_pooled[g * HID + o];
    p[o + 64] = g_pooled[g * HID + o + 64];
    __syncthreads();
    float inv = 1.f / fmaxf(g_counts[g], 1.f);
    float s = 0.f;
#pragma unroll
    for (int k = 0; k < HID; k++) s = fmaf(p[k], Wlin[o * HID + k], s);
    out[g * ODIM + o] = s * inv + blin[o];
}

// ---------------- launch ----------------
extern "C" void kernel_launch(void* const* d_in, const int* in_sizes, int n_in,
                              void* d_out, int out_size) {
    const float* x    = (const float*)d_in[0];
    const int*   ei   = (const int*)d_in[1];
    const int*   batch= (const int*)d_in[2];
    const float* W1l  = (const float*)d_in[3];
    const float* b1l  = (const float*)d_in[4];
    const float* W1r  = (const float*)d_in[5];
    const float* W2l  = (const float*)d_in[6];
    const float* b2l  = (const float*)d_in[7];
    const float* W2r  = (const float*)d_in[8];
    const float* W3l  = (const float*)d_in[9];
    const float* b3l  = (const float*)d_in[10];
    const float* W3r  = (const float*)d_in[11];
    const float* Wlin = (const float*)d_in[12];
    const float* blin = (const float*)d_in[13];
    float* out = (float*)d_out;

    const int* src = ei;
    const int* dst = ei + EE;

    const int ZB = (NN + 255) / 256;       // 196
    const int EB = (EE + 255) / 256;       // 3125

    // CSR build + init
    k_zero<<<ZB, 256>>>();
    k_hist<<<EB, 256>>>(dst);
    k_scan<<<1, 1024>>>();
    k_copy_cursor<<<ZB, 256>>>();
    k_bin<<<EB, 256>>>(src, dst);

    // weight transposes
    k_transpose<<<64, 256>>>(W1l, 0);
    k_transpose<<<64, 256>>>(W1r, 1);
    k_transpose<<<64, 256>>>(W2l, 2);
    k_transpose<<<64, 256>>>(W2r, 3);
    k_transpose<<<64, 256>>>(W3l, 4);
    k_transpose<<<64, 256>>>(W3r, 5);

    const int AGG_B  = (NN * 32 + 255) / 256;  // one warp per node
    const int GEMM_B = (NN + 127) / 128;       // 391

    // layer 1: in = x
    k_aggregate<<<AGG_B, 256>>>(x, -1);
    k_gemm<<<GEMM_B, 256>>>(x, -1, 0, 1, b1l, /*out=*/0, /*relu=*/1);
    // layer 2: in = bufA -> out bufB
    k_aggregate<<<AGG_B, 256>>>(nullptr, 0);
    k_gemm<<<GEMM_B, 256>>>(nullptr, 0, 2, 3, b2l, /*out=*/1, /*relu=*/1);
    // layer 3: in = bufB -> out bufA (no relu)
    k_aggregate<<<AGG_B, 256>>>(nullptr, 1);
    k_gemm<<<GEMM_B, 256>>>(nullptr, 1, 4, 5, b3l, /*out=*/0, /*relu=*/0);

    // pool + final
    const int POOL_W = (NN + 15) / 16;                 // warps
    const int POOL_B = (POOL_W * 32 + 255) / 256;
    k_pool<<<POOL_B, 256>>>(batch);
    k_final<<<NG, ODIM>>>(Wlin, blin, out);
}